// round 15
// baseline (speedup 1.0000x reference)
#include <cuda_runtime.h>
#include <cuda_fp16.h>
#include <cuda_fp8.h>
#include <cstdint>

#define H 512
#define W 512
#define NPIX (H * W)

// Packed flow-corner table: entry (i,j) = 8 bytes = 4 corners x (f0,f1) in fp8 e4m3:
//   e.x = [c01.f1 c01.f0 c00.f1 c00.f0]   e.y = [c11.f1 c11.f0 c10.f1 c10.f0]
// One LDG.64 per bilinear sample. HW fp8->half2 converts keep ALU load low.
__device__ uint2 g_F[NPIX];   // 2 MB

__device__ __forceinline__ uint16_t pack_fp8x2(float a, float b) {
    return (uint16_t)__nv_cvt_float2_to_fp8x2(make_float2(a, b),
                                              __NV_SATFINITE, __NV_E4M3);
}

// Vectorized build: each thread builds 8 consecutive entries of one row.
__global__ void build_F_kernel(const float* __restrict__ flow) {
    int t = blockIdx.x * blockDim.x + threadIdx.x;
    if (t < NPIX / 8) {
        int i  = t >> 6;
        int j0 = (t & 63) << 3;
        int r0 = i << 9;
        int r1 = min(i + 1, H - 1) << 9;

        float v[2][2][9];
        #pragma unroll
        for (int r = 0; r < 2; r++) {
            int rb = (r == 0) ? r0 : r1;
            #pragma unroll
            for (int c = 0; c < 2; c++) {
                const float* src = flow + c * NPIX + rb + j0;
                float4 A = *reinterpret_cast<const float4*>(src);
                float4 B = *reinterpret_cast<const float4*>(src + 4);
                v[r][c][0] = A.x; v[r][c][1] = A.y; v[r][c][2] = A.z; v[r][c][3] = A.w;
                v[r][c][4] = B.x; v[r][c][5] = B.y; v[r][c][6] = B.z; v[r][c][7] = B.w;
                v[r][c][8] = flow[c * NPIX + rb + min(j0 + 8, W - 1)];
            }
        }
        uint16_t p0[9], p1[9];
        #pragma unroll
        for (int k = 0; k < 9; k++) {
            p0[k] = pack_fp8x2(v[0][0][k], v[0][1][k]);
            p1[k] = pack_fp8x2(v[1][0][k], v[1][1][k]);
        }
        uint4* dst = reinterpret_cast<uint4*>(g_F + (r0 | j0));
        #pragma unroll
        for (int q = 0; q < 4; q++) {
            int k = q * 2;
            uint4 two;
            two.x = (uint32_t)p0[k]     | ((uint32_t)p0[k + 1] << 16);
            two.y = (uint32_t)p1[k]     | ((uint32_t)p1[k + 1] << 16);
            two.z = (uint32_t)p0[k + 1] | ((uint32_t)p0[k + 2] << 16);
            two.w = (uint32_t)p1[k + 1] | ((uint32_t)p1[k + 2] << 16);
            dst[q] = two;
        }
    }
}

__device__ __forceinline__ float2 unpack_fp8x2(uint16_t v) {
    __half2_raw hr = __nv_cvt_fp8x2_to_halfraw2((__nv_fp8x2_storage_t)v, __NV_E4M3);
    __half2 h = *reinterpret_cast<__half2*>(&hr);
    return __half22float2(h);
}

#define OUT_SCALE (512.0f / 511.0f)

// Table-independent setup (nearest == bilinear with xf=yf=1).
__device__ __forceinline__ int point_setup(float x, float y, bool bilinear,
                                           float& xf, float& yf, float& a0, float& a1) {
    int x0, y0;
    if (bilinear) {
        float xt = truncf(x);
        float yt = truncf(y);
        xf = x - xt;
        yf = y - yt;
        x0 = (int)xt;
        y0 = (int)yt;
    } else {
        x0 = min((int)rintf(x), H - 1);
        y0 = min((int)rintf(y), W - 1);
        xf = 1.0f;
        yf = 1.0f;
    }
    a0 = (float)(x0 + 1) - yf;
    a1 = (float)(y0 + 1) - xf;
    return (x0 << 9) | y0;
}

__device__ __forceinline__ float2 point_finish(float xf, float yf, float a0, float a1,
                                               uint2 e) {
    float2 c00 = unpack_fp8x2((uint16_t)(e.x & 0xFFFF));
    float2 c01 = unpack_fp8x2((uint16_t)(e.x >> 16));
    float2 c10 = unpack_fp8x2((uint16_t)(e.y & 0xFFFF));
    float2 c11 = unpack_fp8x2((uint16_t)(e.y >> 16));
    float oxf = 1.0f - xf;
    float oyf = 1.0f - yf;
    float w00 = xf * yf;
    float w10 = xf * oyf;
    float w01 = oxf * yf;
    float w11 = oxf * oyf;
    float bf0 = fmaf(w00, c00.x, fmaf(w10, c10.x, fmaf(w01, c01.x, w11 * c11.x)));
    float bf1 = fmaf(w00, c00.y, fmaf(w10, c10.y, fmaf(w01, c01.y, w11 * c11.y)));
    return make_float2((a0 + bf0) * OUT_SCALE, (a1 + bf1) * OUT_SCALE);
}

// PDL: starts while build_F_kernel drains; table-independent work pre-sync.
__global__ void sample_kernel(const float4* __restrict__ pts,
                              float4* __restrict__ out,
                              const int* __restrict__ intep,
                              int n_vec) {
    int idx = blockIdx.x * blockDim.x + threadIdx.x;
    bool active = idx < n_vec;

    float4 p = make_float4(0.f, 0.f, 0.f, 0.f);
    bool bilinear = true;
    if (active) {
        bilinear = (*intep) != 0;
        p = __ldcs(pts + idx);           // long-latency DRAM load, pre-sync
    }
    float xf0, yf0, A0, A1, xf1, yf1, B0, B1;
    int k0 = point_setup(p.x, p.y, bilinear, xf0, yf0, A0, A1);
    int k1 = point_setup(p.z, p.w, bilinear, xf1, yf1, B0, B1);

    cudaGridDependencySynchronize();

    if (!active) return;
    uint2 e0 = __ldg(g_F + k0);
    uint2 e1 = __ldg(g_F + k1);
    float2 r0 = point_finish(xf0, yf0, A0, A1, e0);
    float2 r1 = point_finish(xf1, yf1, B0, B1, e1);
    __stcs(out + idx, make_float4(r0.x, r0.y, r1.x, r1.y));
}

extern "C" void kernel_launch(void* const* d_in, const int* in_sizes, int n_in,
                              void* d_out, int out_size) {
    const float* point = (const float*)d_in[0];   // (1, N, 2)
    const float* flow  = (const float*)d_in[1];   // (1, 2, 512, 512)
    const int*   intep = (const int*)d_in[2];

    static bool carveout_set = false;
    if (!carveout_set) {
        cudaFuncSetAttribute(sample_kernel,
                             cudaFuncAttributePreferredSharedMemoryCarveout, 0);
        cudaFuncSetAttribute(build_F_kernel,
                             cudaFuncAttributePreferredSharedMemoryCarveout, 0);
        carveout_set = true;
    }

    build_F_kernel<<<(NPIX / 8 + 255) / 256, 256>>>(flow);

    int n_vec = out_size / 4;  // 2 points per float4

    cudaLaunchConfig_t cfg = {};
    cfg.gridDim = dim3((n_vec + 255) / 256, 1, 1);
    cfg.blockDim = dim3(256, 1, 1);
    cfg.dynamicSmemBytes = 0;
    cfg.stream = 0;
    cudaLaunchAttribute attrs[1];
    attrs[0].id = cudaLaunchAttributeProgrammaticStreamSerialization;
    attrs[0].val.programmaticStreamSerializationAllowed = 1;
    cfg.attrs = attrs;
    cfg.numAttrs = 1;
    cudaLaunchKernelEx(&cfg, sample_kernel,
                       (const float4*)point, (float4*)d_out, intep, n_vec);
}